// round 3
// baseline (speedup 1.0000x reference)
#include <cuda_runtime.h>
#include <cuda_bf16.h>

#define BS   8
#define CH   256
#define TLEN 512
#define PBIN 16
#define SRAT 4

// 4 MB transposed-input scratch: (b, t, c) layout so channel gathers coalesce.
__device__ float g_tr[BS * TLEN * CH];

// ---------------------------------------------------------------------------
// Kernel 1: transpose (b, ch, t) -> (b, t, ch), tiled 32x32 through smem.
// ---------------------------------------------------------------------------
__global__ void transpose_kernel(const float* __restrict__ in) {
    __shared__ float tile[32][33];
    const int b  = blockIdx.z;
    const int t0 = blockIdx.x * 32;
    const int c0 = blockIdx.y * 32;
    const int tx = threadIdx.x;          // 0..31
    const int ty = threadIdx.y;          // 0..7

    const float* inb  = in   + (size_t)b * CH * TLEN;
    float*       outb = g_tr + (size_t)b * TLEN * CH;

    #pragma unroll
    for (int j = 0; j < 32; j += 8)
        tile[ty + j][tx] = inb[(size_t)(c0 + ty + j) * TLEN + (t0 + tx)];
    __syncthreads();
    #pragma unroll
    for (int j = 0; j < 32; j += 8)
        outb[(size_t)(t0 + ty + j) * CH + (c0 + tx)] = tile[tx][ty + j];
}

// ---------------------------------------------------------------------------
// Kernel 2: 256-thread block = 4 ROIs (64 threads each, thread owns 4 chans).
//   Per-ROI subgroup synchronized with its own named barrier (no cross-ROI
//   coupling). Two 8-bin passes halve the staging smem (36KB/block total),
//   so occupancy is register-limited at 4 blocks/SM (32 warps).
// ---------------------------------------------------------------------------
__global__ __launch_bounds__(256, 4) void roialign_kernel(const float* __restrict__ rois,
                                                          float4* __restrict__ out) {
    const int sub = threadIdx.x >> 6;        // which ROI in this block (0..3)
    const int l   = threadIdx.x & 63;        // lane within ROI subgroup
    const int n   = blockIdx.x * 4 + sub;    // ROI index

    __shared__ uint4  s_desc [4][PBIN * SRAT];   // 64 sample descriptors / ROI
    __shared__ float4 s_stage[4][8][64];         // 8-bin staging / ROI (rotated)

    const int bar_id = sub + 1;

    // ---- Phase A: per-sample descriptors (thread i == sample i) ----
    {
        const float bf    = __ldg(&rois[n * 3 + 0]);
        const float start = __ldg(&rois[n * 3 + 1]);
        const float end   = __ldg(&rois[n * 3 + 2]);
        const float roi_len = fmaxf(end - start, 1.0f);
        const float bin     = roi_len * (1.0f / (float)PBIN);

        const int p = l >> 2;                // bin
        const int s = l & 3;                 // sample
        const float x = start + ((float)p + ((float)s + 0.5f) * 0.25f) * bin;
        const bool valid = (x >= -1.0f) && (x <= (float)TLEN);
        const float xc = fminf(fmaxf(x, 0.0f), (float)(TLEN - 1));
        const int xl = (int)floorf(xc);
        const int xh = min(xl + 1, TLEN - 1);
        const float lx = xc - (float)xl;
        const int b = (int)bf;

        uint4 d;
        d.x = (unsigned)(((b << 9) + xl) << 10);   // byte offset of row xl
        d.y = (unsigned)(((b << 9) + xh) << 10);   // byte offset of row xh
        d.z = __float_as_uint(valid ? (1.0f - lx) : 0.0f);
        d.w = __float_as_uint(valid ? lx : 0.0f);
        s_desc[sub][l] = d;
    }
    asm volatile("bar.sync %0, %1;" :: "r"(bar_id), "r"(64) : "memory");

    const char* base = (const char*)g_tr + l * 16;     // this thread's channels
    float4* outn = out + (size_t)n * (CH * PBIN / 4);
    const float* st = (const float*)s_stage[sub];

    #pragma unroll
    for (int h = 0; h < 2; h++) {
        // ---- Phase B: gather + accumulate 8 bins, stage with rotation r ----
        #pragma unroll 2
        for (int r = 0; r < 8; r++) {
            const int p = 8 * h + r;
            float4 acc = make_float4(0.0f, 0.0f, 0.0f, 0.0f);
            #pragma unroll
            for (int s = 0; s < SRAT; s++) {
                const uint4 d = s_desc[sub][p * SRAT + s];
                const float4 vlo = *(const float4*)(base + d.x);
                const float4 vhi = *(const float4*)(base + d.y);
                const float wlo = __uint_as_float(d.z);
                const float whi = __uint_as_float(d.w);
                acc.x += vlo.x * wlo + vhi.x * whi;
                acc.y += vlo.y * wlo + vhi.y * whi;
                acc.z += vlo.z * wlo + vhi.z * whi;
                acc.w += vlo.w * wlo + vhi.w * whi;
            }
            acc.x *= 0.25f; acc.y *= 0.25f; acc.z *= 0.25f; acc.w *= 0.25f;
            s_stage[sub][r][(l + r) & 63] = acc;       // conflict-free STS.128
        }
        asm volatile("bar.sync %0, %1;" :: "r"(bar_id), "r"(64) : "memory");

        // ---- Phase C: coalesced writeback of this half ----
        // m enumerates the 512 output float4s of this half; lanes conflict-free.
        #pragma unroll
        for (int k = 0; k < 8; k++) {
            const int m  = l + 64 * k;
            const int c  = m >> 1;           // channel
            const int g2 = m & 1;            // which float4 within the half
            float4 v;
            #pragma unroll
            for (int j = 0; j < 4; j++) {
                const int r = 4 * g2 + j;    // staged bin row
                ((float*)&v)[j] = st[r * 256 + (((c >> 2) + r) & 63) * 4 + (c & 3)];
            }
            outn[c * 4 + 2 * h + g2] = v;
        }
        asm volatile("bar.sync %0, %1;" :: "r"(bar_id), "r"(64) : "memory");
    }
}

extern "C" void kernel_launch(void* const* d_in, const int* in_sizes, int n_in,
                              void* d_out, int out_size) {
    const float* input = (const float*)d_in[0];
    const float* rois  = (const float*)d_in[1];
    float4*      out   = (float4*)d_out;

    const int N = in_sizes[1] / 3;       // 2048 ROIs

    dim3 tgrid(TLEN / 32, CH / 32, BS);  // (16, 8, 8)
    dim3 tblk(32, 8);
    transpose_kernel<<<tgrid, tblk>>>(input);

    roialign_kernel<<<N / 4, 256>>>(rois, out);
}